// round 13
// baseline (speedup 1.0000x reference)
#include <cuda_runtime.h>

// DropBlock: x [64,256,64,64] f32, u [58,58] f32. BLOCK_SIZE=7, DROP_PROB=0.1
//
// Mask is ~99.4% zeros (P(keep)=0.9^49~0.6%). Strategy:
//   k1: ballot bitboards -> compact list of kept float4 columns (+multipliers)
//   zerofill: pure 268MB store of zeros (no loads/branches) — PDL-overlaps k1
//   fixup: one warp per (n,c) plane rewrites only kept columns with x*m
// PDL preserves completion order, so fixup (stream-ordered after zerofill)
// runs after both zerofill and k1.

#define H 64
#define W 64
#define HW 4096
#define US 58           // H - BS + 1
#define BS 7
#define DROP_PROB 0.1f

typedef unsigned long long u64;

__device__ int    d_count;                       // # kept float4 columns (0..1024)
__device__ int    d_keep_q[1024];                // kept float4 column indices
__device__ __align__(16) float4 d_keep_m[1024];  // their multiplier float4s

// ---------------- Kernel 1: mask -> compact kept list ----------------
__global__ __launch_bounds__(1024)
void build_mask_kernel(const float* __restrict__ u) {
    cudaTriggerProgrammaticLaunchCompletion();

    __shared__ u64 s_hdil[US];
    __shared__ u64 s_vdil[H];
    __shared__ int s_sum;
    __shared__ int s_cnt;

    int tid  = threadIdx.x;
    int lane = tid & 31;
    int warp = tid >> 5;
    if (tid == 0) { s_sum = 0; s_cnt = 0; }

    int rowA = warp;          // always < 58
    int rowB = warp + 32;     // valid if < 58
    const float* rA = u + rowA * US;

    float a0 = rA[lane];
    float a1 = (lane + 32 < US) ? rA[lane + 32] : 1.0f;
    float b0 = 1.0f, b1 = 1.0f;
    if (rowB < US) {
        const float* rB = u + rowB * US;
        b0 = rB[lane];
        b1 = (lane + 32 < US) ? rB[lane + 32] : 1.0f;
    }

    {
        unsigned m0 = __ballot_sync(0xFFFFFFFFu, a0 < DROP_PROB);
        unsigned m1 = __ballot_sync(0xFFFFFFFFu, a1 < DROP_PROB);
        u64 b = (u64)m0 | ((u64)m1 << 32);
        u64 h = b;
        #pragma unroll
        for (int s = 1; s < BS; s++) h |= b << s;
        if (lane == 0) s_hdil[rowA] = h;
    }
    {
        unsigned m0 = __ballot_sync(0xFFFFFFFFu, b0 < DROP_PROB);
        unsigned m1 = __ballot_sync(0xFFFFFFFFu, b1 < DROP_PROB);
        if (rowB < US && lane == 0) {
            u64 b = (u64)m0 | ((u64)m1 << 32);
            u64 h = b;
            #pragma unroll
            for (int s = 1; s < BS; s++) h |= b << s;
            s_hdil[rowB] = h;
        }
    }
    __syncthreads();

    if (tid < H) {
        int i0 = tid - (BS - 1); if (i0 < 0) i0 = 0;
        int i1 = tid;            if (i1 > US - 1) i1 = US - 1;
        u64 v = 0ULL;
        for (int i = i0; i <= i1; i++) v |= s_hdil[i];
        s_vdil[tid] = v;
        int keep = W - __popcll(v);
        #pragma unroll
        for (int off = 16; off > 0; off >>= 1)
            keep += __shfl_down_sync(0xFFFFFFFFu, keep, off);
        if (lane == 0) atomicAdd(&s_sum, keep);
    }
    __syncthreads();

    float scale = (float)HW / (float)s_sum;

    // thread tid <-> float4 column q (1024 threads = 1024 columns)
    int q = tid;
    int y = q >> 4;
    int x = (q & 15) * 4;
    u64 v = s_vdil[y];
    unsigned dropped4 = (unsigned)((v >> x) & 0xFULL);
    if (dropped4 != 0xFu) {              // at least one kept pixel
        float4 f;
        f.x = (dropped4 & 1u) ? 0.0f : scale;
        f.y = (dropped4 & 2u) ? 0.0f : scale;
        f.z = (dropped4 & 4u) ? 0.0f : scale;
        f.w = (dropped4 & 8u) ? 0.0f : scale;
        int pos = atomicAdd(&s_cnt, 1);
        d_keep_q[pos] = q;
        d_keep_m[pos] = f;
    }
    __syncthreads();
    if (tid == 0) d_count = s_cnt;
}

// ---------------- Zerofill: pure write stream (PDL secondary) ----------
// No loads, no branches, no dependence on k1 -> no GridDepSync.
__global__ __launch_bounds__(256)
void zerofill_kernel(float4* __restrict__ out4) {
    int idx = blockIdx.x * 256 + threadIdx.x;
    out4[idx] = make_float4(0.0f, 0.0f, 0.0f, 0.0f);
}

__global__ __launch_bounds__(256)
void zerofill_kernel_guard(float4* __restrict__ out4, int n4) {
    int idx = blockIdx.x * 256 + threadIdx.x;
    if (idx < n4) out4[idx] = make_float4(0.0f, 0.0f, 0.0f, 0.0f);
}

// ---------------- Fixup: rewrite kept columns --------------------------
// One warp per (n,c) plane; lanes loop over the kept-column list.
__global__ __launch_bounds__(256)
void fixup_kernel(const float4* __restrict__ x4,
                  float4* __restrict__ out4,
                  int planes) {
    __shared__ int s_cnt;
    if (threadIdx.x == 0) s_cnt = d_count;
    __syncthreads();
    int cnt = s_cnt;

    int warp = threadIdx.x >> 5;
    int lane = threadIdx.x & 31;
    int plane = blockIdx.x * 8 + warp;
    if (plane >= planes) return;
    int base = plane << 10;              // *1024 float4s per plane

    for (int k = lane; k < cnt; k += 32) {
        int q = d_keep_q[k];
        float4 m = d_keep_m[k];
        float4 v = x4[base + q];
        v.x *= m.x; v.y *= m.y; v.z *= m.z; v.w *= m.w;
        out4[base + q] = v;
    }
}

extern "C" void kernel_launch(void* const* d_in, const int* in_sizes, int n_in,
                              void* d_out, int out_size) {
    const float* x = (const float*)d_in[0];
    const float* u = (const float*)d_in[1];
    float* out = (float*)d_out;

    int n4 = out_size / 4;               // 16,777,216 float4s (2^24)
    int planes = n4 >> 10;               // 16384 (n,c) planes

    // k1: mask + kept list; triggers PDL immediately.
    build_mask_kernel<<<1, 1024>>>(u);

    // zerofill as PDL secondary: starts while k1 runs (no data dependency;
    // PDL preserves completion order so fixup below is ordered after both).
    cudaLaunchConfig_t cfg = {};
    cfg.blockDim = dim3(256, 1, 1);
    cfg.dynamicSmemBytes = 0;
    cfg.stream = 0;
    cudaLaunchAttribute attr[1];
    attr[0].id = cudaLaunchAttributeProgrammaticStreamSerialization;
    attr[0].val.programmaticStreamSerializationAllowed = 1;
    cfg.attrs = attr;
    cfg.numAttrs = 1;

    if ((n4 & 255) == 0) {
        cfg.gridDim = dim3(n4 / 256, 1, 1);
        cudaLaunchKernelEx(&cfg, zerofill_kernel, (float4*)out);
    } else {
        cfg.gridDim = dim3((n4 + 255) / 256, 1, 1);
        cudaLaunchKernelEx(&cfg, zerofill_kernel_guard, (float4*)out, n4);
    }

    // fixup: normal stream-ordered launch (after zerofill completes).
    int fblocks = (planes + 7) / 8;
    fixup_kernel<<<fblocks, 256>>>((const float4*)x, (float4*)out, planes);
}

// round 14
// speedup vs baseline: 1.5122x; 1.5122x over previous
#include <cuda_runtime.h>

// DropBlock: x [64,256,64,64] f32, u [58,58] f32. BLOCK_SIZE=7, DROP_PROB=0.1
// Mask is ~99.4% zeros. Single gated pass (best algorithm, R12), refined:
//  - 32B (2 float4) per thread: halves gating overhead per byte stored
//  - gate on 1-byte keep flags (ushort covers both columns); multiplier
//    float4s loaded only for kept columns
// k1 (ballot bitboards -> mult table + keep flags) --PDL--> k2.

#define H 64
#define W 64
#define HW 4096
#define US 58           // H - BS + 1
#define BS 7
#define DROP_PROB 0.1f
#define K2_THREADS 256

typedef unsigned long long u64;

__device__ __align__(16) float d_mult[HW];        // 1024 float4 multipliers
__device__ __align__(4)  unsigned char d_keep8[1024]; // 1 = column has a kept pixel

// ---------------- Kernel 1: mask via warp ballots ----------------
__global__ __launch_bounds__(1024)
void build_mask_kernel(const float* __restrict__ u) {
    cudaTriggerProgrammaticLaunchCompletion();

    __shared__ u64 s_hdil[US];
    __shared__ u64 s_vdil[H];
    __shared__ int s_sum;

    int tid  = threadIdx.x;
    int lane = tid & 31;
    int warp = tid >> 5;
    if (tid == 0) s_sum = 0;

    int rowA = warp;          // always < 58
    int rowB = warp + 32;     // valid if < 58
    const float* rA = u + rowA * US;

    float a0 = rA[lane];
    float a1 = (lane + 32 < US) ? rA[lane + 32] : 1.0f;
    float b0 = 1.0f, b1 = 1.0f;
    if (rowB < US) {
        const float* rB = u + rowB * US;
        b0 = rB[lane];
        b1 = (lane + 32 < US) ? rB[lane + 32] : 1.0f;
    }

    {
        unsigned m0 = __ballot_sync(0xFFFFFFFFu, a0 < DROP_PROB);
        unsigned m1 = __ballot_sync(0xFFFFFFFFu, a1 < DROP_PROB);
        u64 b = (u64)m0 | ((u64)m1 << 32);
        u64 h = b;
        #pragma unroll
        for (int s = 1; s < BS; s++) h |= b << s;
        if (lane == 0) s_hdil[rowA] = h;
    }
    {
        unsigned m0 = __ballot_sync(0xFFFFFFFFu, b0 < DROP_PROB);
        unsigned m1 = __ballot_sync(0xFFFFFFFFu, b1 < DROP_PROB);
        if (rowB < US && lane == 0) {
            u64 b = (u64)m0 | ((u64)m1 << 32);
            u64 h = b;
            #pragma unroll
            for (int s = 1; s < BS; s++) h |= b << s;
            s_hdil[rowB] = h;
        }
    }
    __syncthreads();

    if (tid < H) {
        int i0 = tid - (BS - 1); if (i0 < 0) i0 = 0;
        int i1 = tid;            if (i1 > US - 1) i1 = US - 1;
        u64 v = 0ULL;
        for (int i = i0; i <= i1; i++) v |= s_hdil[i];
        s_vdil[tid] = v;
        int keep = W - __popcll(v);
        #pragma unroll
        for (int off = 16; off > 0; off >>= 1)
            keep += __shfl_down_sync(0xFFFFFFFFu, keep, off);
        if (lane == 0) atomicAdd(&s_sum, keep);
    }
    __syncthreads();

    float scale = (float)HW / (float)s_sum;

    // thread tid <-> float4 column q
    int q = tid;
    int y = q >> 4;
    int x = (q & 15) * 4;
    u64 v = s_vdil[y];
    unsigned dropped4 = (unsigned)((v >> x) & 0xFULL);
    float4 f;
    f.x = (dropped4 & 1u) ? 0.0f : scale;
    f.y = (dropped4 & 2u) ? 0.0f : scale;
    f.z = (dropped4 & 4u) ? 0.0f : scale;
    f.w = (dropped4 & 8u) ? 0.0f : scale;
    reinterpret_cast<float4*>(d_mult)[q] = f;
    d_keep8[q] = (dropped4 != 0xFu) ? 1 : 0;
}

// ---------------- Kernel 2: gated 32B store stream (PDL consumer) --------
// Each thread owns 2 consecutive float4s (columns q0=even, q1=q0+1).
// Gate on a single ushort (both keep flags); load multipliers/x only if kept.
__global__ __launch_bounds__(K2_THREADS)
void apply_mask_kernel(const float4* __restrict__ x4,
                       float4* __restrict__ out4) {
    int t  = blockIdx.x * K2_THREADS + threadIdx.x;
    int i0 = t << 1;                   // even float4 index

    cudaGridDependencySynchronize();   // d_mult / d_keep8 visible

    int q0 = i0 & 1023;                // even -> q0 even, q1 = q0+1
    unsigned short kk = *reinterpret_cast<const unsigned short*>(&d_keep8[q0]);

    float4 r0 = make_float4(0.f, 0.f, 0.f, 0.f);
    float4 r1 = make_float4(0.f, 0.f, 0.f, 0.f);
    if (kk != 0) {
        const float4* m4 = reinterpret_cast<const float4*>(d_mult);
        float4 m0 = __ldg(&m4[q0]);
        float4 m1 = __ldg(&m4[q0 + 1]);
        float4 v0 = x4[i0];
        float4 v1 = x4[i0 + 1];
        r0.x = v0.x * m0.x; r0.y = v0.y * m0.y; r0.z = v0.z * m0.z; r0.w = v0.w * m0.w;
        r1.x = v1.x * m1.x; r1.y = v1.y * m1.y; r1.z = v1.z * m1.z; r1.w = v1.w * m1.w;
    }
    out4[i0]     = r0;
    out4[i0 + 1] = r1;
}

// Guarded fallback (odd sizes).
__global__ __launch_bounds__(K2_THREADS)
void apply_mask_kernel_guard(const float4* __restrict__ x4,
                             float4* __restrict__ out4, int n4) {
    int idx = blockIdx.x * K2_THREADS + threadIdx.x;
    cudaGridDependencySynchronize();
    if (idx >= n4) return;
    int q = idx & 1023;
    float4 r = make_float4(0.f, 0.f, 0.f, 0.f);
    if (d_keep8[q]) {
        const float4* m4 = reinterpret_cast<const float4*>(d_mult);
        float4 m = __ldg(&m4[q]);
        float4 v = x4[idx];
        r.x = v.x * m.x; r.y = v.y * m.y; r.z = v.z * m.z; r.w = v.w * m.w;
    }
    out4[idx] = r;
}

extern "C" void kernel_launch(void* const* d_in, const int* in_sizes, int n_in,
                              void* d_out, int out_size) {
    const float* x = (const float*)d_in[0];
    const float* u = (const float*)d_in[1];
    float* out = (float*)d_out;

    build_mask_kernel<<<1, 1024>>>(u);

    int n4 = out_size / 4;               // 16,777,216 float4s (2^24)

    cudaLaunchConfig_t cfg = {};
    cfg.blockDim = dim3(K2_THREADS, 1, 1);
    cfg.dynamicSmemBytes = 0;
    cfg.stream = 0;
    cudaLaunchAttribute attr[1];
    attr[0].id = cudaLaunchAttributeProgrammaticStreamSerialization;
    attr[0].val.programmaticStreamSerializationAllowed = 1;
    cfg.attrs = attr;
    cfg.numAttrs = 1;

    if ((n4 % (2 * K2_THREADS)) == 0) {
        cfg.gridDim = dim3(n4 / (2 * K2_THREADS), 1, 1);   // 32768 blocks
        cudaLaunchKernelEx(&cfg, apply_mask_kernel,
                           (const float4*)x, (float4*)out);
    } else {
        cfg.gridDim = dim3((n4 + K2_THREADS - 1) / K2_THREADS, 1, 1);
        cudaLaunchKernelEx(&cfg, apply_mask_kernel_guard,
                           (const float4*)x, (float4*)out, n4);
    }
}